// round 1
// baseline (speedup 1.0000x reference)
#include <cuda_runtime.h>

// ---------------- problem constants ----------------
#define NB 4
#define NC 512
#define NG 2048
#define CH 3
#define NP 3
#define NBAS 10
#define OC 64
#define EPSF 1e-6f
#define BNEPS 1e-5f
#define LOG2E_F 1.4426950408889634f
#define PI2F 6.283185307179586f
#define SQRT_2_OVER_NBAS 0.4472135954999579f

#define SPLIT 2
#define NCHUNK (NC / SPLIT)   // 256
#define TILE_G 32
#define GTILES (NG / TILE_G)  // 64

#define ELEMS (NB * NG * CH * NP)  // 73728

// output offsets (flattened tuple concat: y_out, n_f, fourier, n_h1, h0_f)
#define OFF_NF  (NB * NG * OC)        // 524288
#define OFF_FP  (OFF_NF + ELEMS)      // 598016
#define OFF_NH1 (OFF_FP + ELEMS)      // 671744
#define OFF_H0  (OFF_NH1 + ELEMS)     // 745472

// ---------------- scratch (no allocs allowed) ----------------
__device__ float g_ph0[SPLIT * ELEMS];
__device__ float g_ph1[SPLIT * ELEMS];
__device__ float g_pos[ELEMS];     // n_h1 + fourier (conv input)
__device__ float g_conv[ELEMS];    // conv output (pre-BN)
__device__ float g_bn[2 * CH * NP];  // [0..8] mean, [9..17] rstd

__device__ __forceinline__ float ex2f(float x) {
    float y;
    asm("ex2.approx.ftz.f32 %0, %1;" : "=f"(y) : "f"(x));
    return y;
}

// ---------------- kernel 1: RBF pairwise partial sums ----------------
// grid: NB * GTILES * SPLIT = 512 blocks, block: 96 threads.
// thread (c = tid/32 warp-uniform, lane = g within tile) -> one (b,g,c),
// loops over an nc-chunk of 256 context points, accumulating h0/h1 for all 3 p.
__global__ __launch_bounds__(CH * TILE_G) void k1_rbf(
    const float* __restrict__ x_c, const float* __restrict__ y_c,
    const float* __restrict__ x_g, const float* __restrict__ sigma)
{
    __shared__ float sx[NCHUNK * CH];
    __shared__ float sy[NCHUNK * CH];

    int unit = blockIdx.x;
    int s  = unit % SPLIT;
    int gt = (unit / SPLIT) % GTILES;
    int b  = unit / (SPLIT * GTILES);

    int lane = threadIdx.x & 31;
    int c    = threadIdx.x >> 5;       // 0..2, uniform per warp
    int g    = gt * TILE_G + lane;
    int n0   = s * NCHUNK;

    const float* xb = x_c + (b * NC + n0) * CH;
    const float* yb = y_c + (b * NC + n0) * CH;
    for (int i = threadIdx.x; i < NCHUNK * CH; i += blockDim.x) {
        sx[i] = xb[i];
        sy[i] = yb[i];
    }
    __syncthreads();

    float xg = x_g[(b * NG + g) * CH + c];

    // fold -0.5 * log2(e) / (scale+eps)^2 into one multiply per p
    float s0 = expf(sigma[0]) + EPSF;
    float s1 = expf(sigma[1]) + EPSF;
    float s2 = expf(sigma[2]) + EPSF;
    float k0 = -0.5f * LOG2E_F / (s0 * s0);
    float k1 = -0.5f * LOG2E_F / (s1 * s1);
    float k2 = -0.5f * LOG2E_F / (s2 * s2);

    float h00 = 0.f, h01 = 0.f, h02 = 0.f;
    float h10 = 0.f, h11 = 0.f, h12 = 0.f;

#pragma unroll 4
    for (int n = 0; n < NCHUNK; n++) {
        float d  = xg - sx[n * CH + c];   // broadcast LDS (warp-uniform addr)
        float t  = d * d;
        float yv = sy[n * CH + c];
        float w0 = ex2f(t * k0);
        float w1 = ex2f(t * k1);
        float w2 = ex2f(t * k2);
        h00 += w0; h10 = fmaf(w0, yv, h10);
        h01 += w1; h11 = fmaf(w1, yv, h11);
        h02 += w2; h12 = fmaf(w2, yv, h12);
    }

    int base = ((b * NG + g) * CH + c) * NP;
    int off  = s * ELEMS + base;
    g_ph0[off + 0] = h00; g_ph0[off + 1] = h01; g_ph0[off + 2] = h02;
    g_ph1[off + 0] = h10; g_ph1[off + 1] = h11; g_ph1[off + 2] = h12;
}

// ---------------- kernel 2: combine partials + Fourier prior + outputs ----------------
__global__ void k2_combine(
    const float* __restrict__ x_g, const float* __restrict__ sigma,
    const float* __restrict__ mu,  const float* __restrict__ eps1,
    const float* __restrict__ b_u, const float* __restrict__ rw,
    float* __restrict__ out)
{
    int idx = blockIdx.x * blockDim.x + threadIdx.x;
    if (idx >= ELEMS) return;
    int p = idx % NP;
    int c = (idx / NP) % CH;
    int g = (idx / (NP * CH)) % NG;
    int b = idx / (NP * CH * NG);

    float h0 = g_ph0[idx] + g_ph0[ELEMS + idx];
    float h1 = g_ph1[idx] + g_ph1[ELEMS + idx];
    float nh1 = h1 / (h0 + EPSF);

    float xg   = x_g[(b * NG + g) * CH + c];
    float wmu  = expf(mu[p]);
    float wstd = 1.0f / (expf(sigma[p]) + EPSF);

    // strict (non-contracted) fp32 to mirror XLA mul-then-add rounding;
    // args can reach ~1e5 so every ulp of the product matters to cos().
    float acc = 0.f;
#pragma unroll
    for (int k = 0; k < NBAS; k++) {
        float e  = eps1[(b * NBAS + k) * NP + p];
        float u  = b_u [(b * NBAS + k) * NP + p];
        float sw = __fadd_rn(wmu, __fmul_rn(wstd, e));
        float sb = __fmul_rn(PI2F, u);
        float arg = __fadd_rn(__fmul_rn(sw, xg), sb);
        acc = __fadd_rn(acc, __fmul_rn(rw[k], cosf(arg)));
    }
    float fp = SQRT_2_OVER_NBAS * acc;

    out[OFF_NH1 + idx] = nh1;
    out[OFF_FP  + idx] = fp;
    out[OFF_H0  + idx] = h0;
    g_pos[idx] = nh1 + fp;
}

// ---------------- kernel 3: depthwise 1D conv along g (per p: ksz 3/5/9) ----------------
__global__ void k3_conv(
    const float* __restrict__ w1, const float* __restrict__ b1,
    const float* __restrict__ w2, const float* __restrict__ b2,
    const float* __restrict__ w3, const float* __restrict__ b3)
{
    int idx = blockIdx.x * blockDim.x + threadIdx.x;
    if (idx >= ELEMS) return;
    int p = idx % NP;
    int c = (idx / NP) % CH;
    int g = (idx / (NP * CH)) % NG;
    int b = idx / (NP * CH * NG);

    const float* w; const float* bias; int ksz, pad;
    if (p == 0)      { w = w1; bias = b1; ksz = 3; pad = 1; }
    else if (p == 1) { w = w2; bias = b2; ksz = 5; pad = 2; }
    else             { w = w3; bias = b3; ksz = 9; pad = 4; }

    float acc = bias[c];
    for (int t = 0; t < ksz; t++) {
        int gi = g - pad + t;
        if (gi >= 0 && gi < NG)
            acc = fmaf(w[c * ksz + t], g_pos[((b * NG + gi) * CH + c) * NP + p], acc);
    }
    g_conv[idx] = acc;
}

// ---------------- kernel 4: BN stats (deterministic tree reduce, 9 blocks) ----------------
__global__ void k4_bnstats()
{
    int cp = blockIdx.x;  // c*3+p
    __shared__ float ssum[256];
    __shared__ float ssq[256];
    int tid = threadIdx.x;
    float s = 0.f, q = 0.f;
    for (int i = tid; i < NB * NG; i += 256) {
        float v = g_conv[i * (CH * NP) + cp];
        s += v;
        q = fmaf(v, v, q);
    }
    ssum[tid] = s; ssq[tid] = q;
    __syncthreads();
    for (int st = 128; st > 0; st >>= 1) {
        if (tid < st) { ssum[tid] += ssum[tid + st]; ssq[tid] += ssq[tid + st]; }
        __syncthreads();
    }
    if (tid == 0) {
        const float invn = 1.0f / (float)(NB * NG);
        float m   = ssum[0] * invn;
        float var = ssq[0] * invn - m * m;
        g_bn[cp]     = m;
        g_bn[9 + cp] = rsqrtf(var + BNEPS);
    }
}

// ---------------- kernel 5: BN apply + n_f + final linear (18 -> 64) ----------------
__global__ __launch_bounds__(OC) void k5_final(
    const float* __restrict__ gamma, const float* __restrict__ beta,
    const float* __restrict__ gw,    const float* __restrict__ gb,
    float* __restrict__ out)
{
    int pos = blockIdx.x;  // b*NG + g
    __shared__ float feat[18];
    int tid = threadIdx.x;

    if (tid < 9) {
        int c = tid / 3, p = tid % 3;
        float v = (g_conv[pos * 9 + tid] - g_bn[tid]) * g_bn[9 + tid];
        v = v * gamma[p * CH + c] + beta[p * CH + c];
        feat[9 + tid] = v;
        out[OFF_NF + pos * 9 + tid] = v;
    } else if (tid < 18) {
        feat[tid - 9] = out[OFF_H0 + pos * 9 + (tid - 9)];
    }
    __syncthreads();

    float acc = gb[tid];
#pragma unroll
    for (int f = 0; f < 18; f++)
        acc = fmaf(feat[f], gw[tid * 18 + f], acc);
    out[pos * OC + tid] = acc;
}

// ---------------- launch ----------------
extern "C" void kernel_launch(void* const* d_in, const int* in_sizes, int n_in,
                              void* d_out, int out_size)
{
    const float* x_c   = (const float*)d_in[0];
    const float* y_c   = (const float*)d_in[1];
    const float* x_g   = (const float*)d_in[2];
    const float* sigma = (const float*)d_in[3];
    const float* mu    = (const float*)d_in[4];
    const float* eps1  = (const float*)d_in[5];
    const float* b_u   = (const float*)d_in[6];
    const float* rw    = (const float*)d_in[7];
    const float* w1    = (const float*)d_in[8];
    const float* b1    = (const float*)d_in[9];
    const float* w2    = (const float*)d_in[10];
    const float* b2    = (const float*)d_in[11];
    const float* w3    = (const float*)d_in[12];
    const float* b3    = (const float*)d_in[13];
    const float* gam   = (const float*)d_in[14];
    const float* bet   = (const float*)d_in[15];
    const float* gw    = (const float*)d_in[16];
    const float* gb    = (const float*)d_in[17];
    float* out = (float*)d_out;

    k1_rbf<<<NB * GTILES * SPLIT, CH * TILE_G>>>(x_c, y_c, x_g, sigma);
    k2_combine<<<(ELEMS + 255) / 256, 256>>>(x_g, sigma, mu, eps1, b_u, rw, out);
    k3_conv<<<(ELEMS + 255) / 256, 256>>>(w1, b1, w2, b2, w3, b3);
    k4_bnstats<<<CH * NP, 256>>>();
    k5_final<<<NB * NG, OC>>>(gam, bet, gw, gb, out);
}

// round 2
// speedup vs baseline: 1.0009x; 1.0009x over previous
#include <cuda_runtime.h>

// ---------------- problem constants ----------------
#define NB 4
#define NC 512
#define NG 2048
#define CH 3
#define NP 3
#define NBAS 10
#define OC 64
#define EPSF 1e-6f
#define BNEPS 1e-5f
#define LOG2E_F 1.4426950408889634f
#define PI2F 6.283185307179586f
#define SQRT_2_OVER_NBAS 0.4472135954999579f

#define SPLIT 4
#define NCHUNK (NC / SPLIT)   // 128
#define TILE_G 32
#define GTILES (NG / TILE_G)  // 64

#define ELEMS (NB * NG * CH * NP)  // 73728

// fused combine/conv kernel tiling
#define FG 64                       // g-tile per block
#define FBLOCKS (NB * (NG / FG))    // 128
#define FTHREADS (9 * FG)           // 576
#define HALO 4
#define FGH (FG + 2 * HALO)         // 72

// final kernel tiling
#define K5_POS 32
#define K5_BLOCKS ((NB * NG) / K5_POS)  // 256

// output offsets (flattened tuple concat: y_out, n_f, fourier, n_h1, h0_f)
#define OFF_NF  (NB * NG * OC)        // 524288
#define OFF_FP  (OFF_NF + ELEMS)      // 598016
#define OFF_NH1 (OFF_FP + ELEMS)      // 671744
#define OFF_H0  (OFF_NH1 + ELEMS)     // 745472

// ---------------- scratch (no allocs allowed) ----------------
__device__ float g_ph0[SPLIT * ELEMS];
__device__ float g_ph1[SPLIT * ELEMS];
__device__ float g_conv[ELEMS];             // conv output (pre-BN)
__device__ float g_psum[9 * FBLOCKS];       // per-cp per-block partial sums
__device__ float g_psq [9 * FBLOCKS];       // per-cp per-block partial sum-squares

__device__ __forceinline__ float ex2f(float x) {
    float y;
    asm("ex2.approx.ftz.f32 %0, %1;" : "=f"(y) : "f"(x));
    return y;
}

// ---------------- kernel 1: RBF pairwise partial sums ----------------
// grid: NB * GTILES * SPLIT = 1024 blocks, block: 96 threads.
// thread (c = tid/32 warp-uniform, lane = g within tile) -> one (b,g,c),
// loops over an nc-chunk of 128 context points, accumulating h0/h1 for all 3 p.
__global__ __launch_bounds__(CH * TILE_G) void k1_rbf(
    const float* __restrict__ x_c, const float* __restrict__ y_c,
    const float* __restrict__ x_g, const float* __restrict__ sigma)
{
    __shared__ float sx[NCHUNK * CH];
    __shared__ float sy[NCHUNK * CH];

    int unit = blockIdx.x;
    int s  = unit % SPLIT;
    int gt = (unit / SPLIT) % GTILES;
    int b  = unit / (SPLIT * GTILES);

    int lane = threadIdx.x & 31;
    int c    = threadIdx.x >> 5;       // 0..2, uniform per warp
    int g    = gt * TILE_G + lane;
    int n0   = s * NCHUNK;

    const float* xb = x_c + (b * NC + n0) * CH;
    const float* yb = y_c + (b * NC + n0) * CH;
    for (int i = threadIdx.x; i < NCHUNK * CH; i += blockDim.x) {
        sx[i] = xb[i];
        sy[i] = yb[i];
    }
    __syncthreads();

    float xg = x_g[(b * NG + g) * CH + c];

    // fold -0.5 * log2(e) / (scale+eps)^2 into one multiply per p
    float s0 = expf(sigma[0]) + EPSF;
    float s1 = expf(sigma[1]) + EPSF;
    float s2 = expf(sigma[2]) + EPSF;
    float k0 = -0.5f * LOG2E_F / (s0 * s0);
    float k1 = -0.5f * LOG2E_F / (s1 * s1);
    float k2 = -0.5f * LOG2E_F / (s2 * s2);

    float h00 = 0.f, h01 = 0.f, h02 = 0.f;
    float h10 = 0.f, h11 = 0.f, h12 = 0.f;

#pragma unroll 4
    for (int n = 0; n < NCHUNK; n++) {
        float d  = xg - sx[n * CH + c];   // broadcast LDS (warp-uniform addr)
        float t  = d * d;
        float yv = sy[n * CH + c];
        float w0 = ex2f(t * k0);
        float w1 = ex2f(t * k1);
        float w2 = ex2f(t * k2);
        h00 += w0; h10 = fmaf(w0, yv, h10);
        h01 += w1; h11 = fmaf(w1, yv, h11);
        h02 += w2; h12 = fmaf(w2, yv, h12);
    }

    int base = ((b * NG + g) * CH + c) * NP;
    int off  = s * ELEMS + base;
    g_ph0[off + 0] = h00; g_ph0[off + 1] = h01; g_ph0[off + 2] = h02;
    g_ph1[off + 0] = h10; g_ph1[off + 1] = h11; g_ph1[off + 2] = h12;
}

// ---------------- kernel F: combine + Fourier prior + depthwise conv + BN partials ----------------
// grid: 128 blocks (b x g-tile of 64), 576 threads.
// Phase 1: compute pos = n_h1 + fourier for g-tile + halo into smem (+ write nh1/fp/h0 outs)
// Phase 2: depthwise conv from smem, write g_conv, block-reduce per-cp sum/sumsq partials.
__global__ __launch_bounds__(FTHREADS) void kF_fused(
    const float* __restrict__ x_g, const float* __restrict__ sigma,
    const float* __restrict__ mu,  const float* __restrict__ eps1,
    const float* __restrict__ b_u, const float* __restrict__ rw,
    const float* __restrict__ w1, const float* __restrict__ b1,
    const float* __restrict__ w2, const float* __restrict__ b2,
    const float* __restrict__ w3, const float* __restrict__ b3,
    float* __restrict__ out)
{
    __shared__ float spos[FGH * 9];       // 648
    __shared__ float ssw[NBAS * 3];       // sample_w per (k,p)
    __shared__ float ssb[NBAS * 3];       // sample_b per (k,p)
    __shared__ float srw[NBAS];
    __shared__ float ssum[9 * FG];
    __shared__ float ssq [9 * FG];

    int tid = threadIdx.x;
    int b   = blockIdx.x / (NG / FG);
    int gt  = blockIdx.x % (NG / FG);
    int g0  = gt * FG;

    // precompute Fourier sample params (strict rounding, matches XLA HLO order)
    if (tid < NBAS * 3) {
        int k = tid / 3, p = tid % 3;
        float wmu  = expf(mu[p]);
        float wstd = 1.0f / (expf(sigma[p]) + EPSF);
        float e = eps1[(b * NBAS + k) * NP + p];
        float u = b_u [(b * NBAS + k) * NP + p];
        ssw[tid] = __fadd_rn(wmu, __fmul_rn(wstd, e));
        ssb[tid] = __fmul_rn(PI2F, u);
    }
    if (tid < NBAS) srw[tid] = rw[tid];
    __syncthreads();

    // Phase 1: pos for tile + halo
    for (int e = tid; e < FGH * 9; e += FTHREADS) {
        int jj = e / 9;
        int cp = e % 9;
        int c = cp / 3, p = cp % 3;
        int g = g0 - HALO + jj;
        float pos = 0.f;
        if (g >= 0 && g < NG) {
            int idx = ((b * NG + g) * CH + c) * NP + p;
            float h0 = g_ph0[idx] + g_ph0[ELEMS + idx]
                     + g_ph0[2 * ELEMS + idx] + g_ph0[3 * ELEMS + idx];
            float h1 = g_ph1[idx] + g_ph1[ELEMS + idx]
                     + g_ph1[2 * ELEMS + idx] + g_ph1[3 * ELEMS + idx];
            float nh1 = h1 / (h0 + EPSF);

            float xg = x_g[(b * NG + g) * CH + c];
            float acc = 0.f;
#pragma unroll
            for (int k = 0; k < NBAS; k++) {
                float arg = __fadd_rn(__fmul_rn(ssw[k * 3 + p], xg), ssb[k * 3 + p]);
                acc = __fadd_rn(acc, __fmul_rn(srw[k], cosf(arg)));
            }
            float fp = SQRT_2_OVER_NBAS * acc;
            pos = nh1 + fp;

            if (jj >= HALO && jj < HALO + FG) {   // owned element -> write outputs
                out[OFF_NH1 + idx] = nh1;
                out[OFF_FP  + idx] = fp;
                out[OFF_H0  + idx] = h0;
            }
        }
        spos[e] = pos;
    }
    __syncthreads();

    // Phase 2: depthwise conv along g + per-cp partial stats
    {
        int cp = tid / FG;         // 0..8
        int j  = tid % FG;         // 0..63
        int c = cp / 3, p = cp % 3;
        int g = g0 + j;

        const float* w; const float* bias; int ksz, pad;
        if (p == 0)      { w = w1; bias = b1; ksz = 3; pad = 1; }
        else if (p == 1) { w = w2; bias = b2; ksz = 5; pad = 2; }
        else             { w = w3; bias = b3; ksz = 9; pad = 4; }

        float acc = bias[c];
        int jj0 = j - pad + HALO;  // >= 0 since pad <= HALO
        for (int t = 0; t < ksz; t++)
            acc = fmaf(w[c * ksz + t], spos[(jj0 + t) * 9 + cp], acc);

        g_conv[((b * NG + g) * CH + c) * NP + p] = acc;
        ssum[cp * FG + j] = acc;
        ssq [cp * FG + j] = acc * acc;
    }
    __syncthreads();

    // tree reduce within each cp's 64 values
    {
        int cp = tid / FG;
        int j  = tid % FG;
        int base = cp * FG;
        for (int st = FG / 2; st > 0; st >>= 1) {
            if (j < st) {
                ssum[base + j] += ssum[base + j + st];
                ssq [base + j] += ssq [base + j + st];
            }
            __syncthreads();
        }
        if (j == 0) {
            g_psum[cp * FBLOCKS + blockIdx.x] = ssum[base];
            g_psq [cp * FBLOCKS + blockIdx.x] = ssq [base];
        }
    }
}

// ---------------- kernel 5: BN finalize + apply + n_f + final linear (18 -> 64) ----------------
// grid: 256 blocks x 256 threads, 32 positions per block; g_w staged in smem.
#define GW_STRIDE 19
__global__ __launch_bounds__(256) void k5_final(
    const float* __restrict__ gamma, const float* __restrict__ beta,
    const float* __restrict__ gw,    const float* __restrict__ gb,
    float* __restrict__ out)
{
    __shared__ float sgw[OC * GW_STRIDE];
    __shared__ float sgb[OC];
    __shared__ float sA[9], sB[9];            // folded BN: v*A + B
    __shared__ float feat[K5_POS * 18];

    int tid = threadIdx.x;
    int pos0 = blockIdx.x * K5_POS;

    // stage weights
    for (int t = tid; t < OC * 18; t += 256)
        sgw[(t / 18) * GW_STRIDE + (t % 18)] = gw[t];
    if (tid < OC) sgb[tid] = gb[tid];

    // finalize BN stats from 128 block partials per cp
    if (tid < 9) {
        float s = 0.f, q = 0.f;
#pragma unroll 8
        for (int i = 0; i < FBLOCKS; i++) {
            s += g_psum[tid * FBLOCKS + i];
            q += g_psq [tid * FBLOCKS + i];
        }
        const float invn = 1.0f / (float)(NB * NG);
        float m   = s * invn;
        float var = q * invn - m * m;
        float rs  = rsqrtf(var + BNEPS);
        int c = tid / 3, p = tid % 3;
        float ga = gamma[p * CH + c];
        float be = beta [p * CH + c];
        sA[tid] = rs * ga;
        sB[tid] = be - m * rs * ga;
    }
    __syncthreads();

    // build feature tile: [pos][0..8]=h0_f, [pos][9..17]=n_f (BN applied)
    for (int t = tid; t < K5_POS * 18; t += 256) {
        int pl = t / 18, k = t % 18;
        int pos = pos0 + pl;
        float v;
        if (k < 9) {
            v = out[OFF_H0 + pos * 9 + k];
        } else {
            int cp = k - 9;
            v = fmaf(g_conv[pos * 9 + cp], sA[cp], sB[cp]);
            out[OFF_NF + pos * 9 + cp] = v;
        }
        feat[pl * 18 + k] = v;
    }
    __syncthreads();

    // 18 -> 64 linear for 32 positions
    int oc = tid % OC;
    int pp = tid / OC;   // 0..3
#pragma unroll
    for (int i = 0; i < K5_POS / 4; i++) {
        int pl = pp * (K5_POS / 4) + i;
        float acc = sgb[oc];
#pragma unroll
        for (int f = 0; f < 18; f++)
            acc = fmaf(feat[pl * 18 + f], sgw[oc * GW_STRIDE + f], acc);
        out[(pos0 + pl) * OC + oc] = acc;
    }
}

// ---------------- launch ----------------
extern "C" void kernel_launch(void* const* d_in, const int* in_sizes, int n_in,
                              void* d_out, int out_size)
{
    const float* x_c   = (const float*)d_in[0];
    const float* y_c   = (const float*)d_in[1];
    const float* x_g   = (const float*)d_in[2];
    const float* sigma = (const float*)d_in[3];
    const float* mu    = (const float*)d_in[4];
    const float* eps1  = (const float*)d_in[5];
    const float* b_u   = (const float*)d_in[6];
    const float* rw    = (const float*)d_in[7];
    const float* w1    = (const float*)d_in[8];
    const float* b1    = (const float*)d_in[9];
    const float* w2    = (const float*)d_in[10];
    const float* b2    = (const float*)d_in[11];
    const float* w3    = (const float*)d_in[12];
    const float* b3    = (const float*)d_in[13];
    const float* gam   = (const float*)d_in[14];
    const float* bet   = (const float*)d_in[15];
    const float* gw    = (const float*)d_in[16];
    const float* gb    = (const float*)d_in[17];
    float* out = (float*)d_out;

    k1_rbf<<<NB * GTILES * SPLIT, CH * TILE_G>>>(x_c, y_c, x_g, sigma);
    kF_fused<<<FBLOCKS, FTHREADS>>>(x_g, sigma, mu, eps1, b_u, rw,
                                    w1, b1, w2, b2, w3, b3, out);
    k5_final<<<K5_BLOCKS, 256>>>(gam, bet, gw, gb, out);
}

// round 3
// speedup vs baseline: 1.0604x; 1.0594x over previous
#include <cuda_runtime.h>

// ---------------- problem constants ----------------
#define NB 4
#define NC 512
#define NG 2048
#define CH 3
#define NP 3
#define NBAS 10
#define OC 64
#define EPSF 1e-6f
#define BNEPS 1e-5f
#define LOG2E_F 1.4426950408889634f
#define PI2F 6.283185307179586f
#define INV2PI_F 0.15915494309189535f
#define PI2_D 6.283185307179586
#define SQRT_2_OVER_NBAS 0.4472135954999579f

#define SPLIT 8
#define NCHUNK (NC / SPLIT)   // 64
#define TILE_G 64
#define GTILES (NG / TILE_G)  // 32

#define ELEMS (NB * NG * CH * NP)  // 73728

// fused combine/conv kernel tiling
#define FG 64                       // g-tile per block
#define FBLOCKS (NB * (NG / FG))    // 128
#define FTHREADS (9 * FG)           // 576
#define HALO 4
#define FGH (FG + 2 * HALO)         // 72

// final kernel tiling
#define K5_POS 32
#define K5_BLOCKS ((NB * NG) / K5_POS)  // 256

// output offsets (flattened tuple concat: y_out, n_f, fourier, n_h1, h0_f)
#define OFF_NF  (NB * NG * OC)        // 524288
#define OFF_FP  (OFF_NF + ELEMS)      // 598016
#define OFF_NH1 (OFF_FP + ELEMS)      // 671744
#define OFF_H0  (OFF_NH1 + ELEMS)     // 745472

// ---------------- scratch (no allocs allowed) ----------------
__device__ float g_ph0[SPLIT * ELEMS];
__device__ float g_ph1[SPLIT * ELEMS];
__device__ float g_conv[ELEMS];             // conv output (pre-BN)
__device__ float g_psum[9 * FBLOCKS];       // per-cp per-block partial sums
__device__ float g_psq [9 * FBLOCKS];       // per-cp per-block partial sum-squares

// ---------------- f32x2 packed helpers ----------------
typedef unsigned long long u64t;

__device__ __forceinline__ float ex2f(float x) {
    float y;
    asm("ex2.approx.ftz.f32 %0, %1;" : "=f"(y) : "f"(x));
    return y;
}
__device__ __forceinline__ u64t f2_add(u64t a, u64t b) {
    u64t r; asm("add.rn.f32x2 %0, %1, %2;" : "=l"(r) : "l"(a), "l"(b)); return r;
}
__device__ __forceinline__ u64t f2_mul(u64t a, u64t b) {
    u64t r; asm("mul.rn.f32x2 %0, %1, %2;" : "=l"(r) : "l"(a), "l"(b)); return r;
}
__device__ __forceinline__ u64t f2_fma(u64t a, u64t b, u64t c) {
    u64t r; asm("fma.rn.f32x2 %0, %1, %2, %3;" : "=l"(r) : "l"(a), "l"(b), "l"(c)); return r;
}
__device__ __forceinline__ u64t f2_pack(float lo, float hi) {
    u64t r; asm("mov.b64 %0, {%1, %2};" : "=l"(r) : "f"(lo), "f"(hi)); return r;
}
__device__ __forceinline__ void f2_unpack(u64t v, float& lo, float& hi) {
    asm("mov.b64 {%0, %1}, %2;" : "=f"(lo), "=f"(hi) : "l"(v));
}

// ---------------- kernel 1: RBF pairwise partial sums (packed f32x2) ----------------
// grid: NB * GTILES * SPLIT = 1024 blocks, block: 192 threads (6 warps).
// warp w: c = w % 3 (uniform), g = gt*64 + (w/3)*32 + lane.
// Each thread loops 32 packed context pairs (NCHUNK=64), accumulating h0/h1 for all 3 p.
__global__ __launch_bounds__(CH * TILE_G) void k1_rbf(
    const float* __restrict__ x_c, const float* __restrict__ y_c,
    const float* __restrict__ x_g, const float* __restrict__ sigma)
{
    // packed pair layout: [(n2*3 + c)] -> {-x(2n2,c), -x(2n2+1,c)}
    __shared__ __align__(8) float sxn[NCHUNK * CH];  // negated x, pair-interleaved
    __shared__ __align__(8) float syp[NCHUNK * CH];

    int unit = blockIdx.x;
    int s  = unit % SPLIT;
    int gt = (unit / SPLIT) % GTILES;
    int b  = unit / (SPLIT * GTILES);

    int lane = threadIdx.x & 31;
    int w    = threadIdx.x >> 5;       // 0..5
    int c    = w % 3;                  // uniform per warp
    int g    = gt * TILE_G + (w / 3) * 32 + lane;
    int n0   = s * NCHUNK;

    const float* xb = x_c + (b * NC + n0) * CH;
    const float* yb = y_c + (b * NC + n0) * CH;
    // stage: element (n, cc) -> slot (n2*3 + cc)*2 + (n&1)
    for (int i = threadIdx.x; i < NCHUNK * CH; i += blockDim.x) {
        int n = i / CH, cc = i % CH;
        int slot = ((n >> 1) * CH + cc) * 2 + (n & 1);
        sxn[slot] = -xb[i];
        syp[slot] =  yb[i];
    }
    __syncthreads();

    float xg = x_g[(b * NG + g) * CH + c];
    u64t xg2 = f2_pack(xg, xg);

    // fold -0.5 * log2(e) / (scale+eps)^2 into one multiply per p
    float s0 = expf(sigma[0]) + EPSF;
    float s1 = expf(sigma[1]) + EPSF;
    float s2 = expf(sigma[2]) + EPSF;
    float k0 = -0.5f * LOG2E_F / (s0 * s0);
    float k1 = -0.5f * LOG2E_F / (s1 * s1);
    float k2 = -0.5f * LOG2E_F / (s2 * s2);
    u64t k02 = f2_pack(k0, k0);
    u64t k12 = f2_pack(k1, k1);
    u64t k22 = f2_pack(k2, k2);

    u64t h0a = 0, h0b = 0, h0c = 0;   // packed accumulators (even/odd n)
    u64t h1a = 0, h1b = 0, h1c = 0;

    const u64t* sx2 = (const u64t*)sxn;
    const u64t* sy2 = (const u64t*)syp;

#pragma unroll 8
    for (int n2 = 0; n2 < NCHUNK / 2; n2++) {
        u64t xv = sx2[n2 * CH + c];   // broadcast LDS.64 (warp-uniform addr)
        u64t yv = sy2[n2 * CH + c];
        u64t d2 = f2_add(xg2, xv);    // xg - x  (x pre-negated)
        u64t t2 = f2_mul(d2, d2);

        float alo, ahi;
        u64t a0 = f2_mul(t2, k02);
        f2_unpack(a0, alo, ahi);
        u64t w0 = f2_pack(ex2f(alo), ex2f(ahi));
        h0a = f2_add(h0a, w0);
        h1a = f2_fma(w0, yv, h1a);

        u64t a1 = f2_mul(t2, k12);
        f2_unpack(a1, alo, ahi);
        u64t w1 = f2_pack(ex2f(alo), ex2f(ahi));
        h0b = f2_add(h0b, w1);
        h1b = f2_fma(w1, yv, h1b);

        u64t a2 = f2_mul(t2, k22);
        f2_unpack(a2, alo, ahi);
        u64t w2 = f2_pack(ex2f(alo), ex2f(ahi));
        h0c = f2_add(h0c, w2);
        h1c = f2_fma(w2, yv, h1c);
    }

    float lo, hi;
    int base = ((b * NG + g) * CH + c) * NP;
    int off  = s * ELEMS + base;
    f2_unpack(h0a, lo, hi); g_ph0[off + 0] = lo + hi;
    f2_unpack(h0b, lo, hi); g_ph0[off + 1] = lo + hi;
    f2_unpack(h0c, lo, hi); g_ph0[off + 2] = lo + hi;
    f2_unpack(h1a, lo, hi); g_ph1[off + 0] = lo + hi;
    f2_unpack(h1b, lo, hi); g_ph1[off + 1] = lo + hi;
    f2_unpack(h1c, lo, hi); g_ph1[off + 2] = lo + hi;
}

// accurate-enough cos for args up to ~1e5: exact-multiple reduction via one DFMA,
// then hardware cos on |r| <= pi (abs err ~2e-7).
__device__ __forceinline__ float cos_red(float arg) {
    float n = rintf(arg * INV2PI_F);
    float r = (float)__fma_rn((double)(-n), PI2_D, (double)arg);
    return __cosf(r);
}

// ---------------- kernel F: combine + Fourier prior + depthwise conv + BN partials ----------------
__global__ __launch_bounds__(FTHREADS) void kF_fused(
    const float* __restrict__ x_g, const float* __restrict__ sigma,
    const float* __restrict__ mu,  const float* __restrict__ eps1,
    const float* __restrict__ b_u, const float* __restrict__ rw,
    const float* __restrict__ w1, const float* __restrict__ b1,
    const float* __restrict__ w2, const float* __restrict__ b2,
    const float* __restrict__ w3, const float* __restrict__ b3,
    float* __restrict__ out)
{
    __shared__ float spos[FGH * 9];       // 648
    __shared__ float ssw[NBAS * 3];
    __shared__ float ssb[NBAS * 3];
    __shared__ float srw[NBAS];
    __shared__ float ssum[9 * FG];
    __shared__ float ssq [9 * FG];

    int tid = threadIdx.x;
    int b   = blockIdx.x / (NG / FG);
    int gt  = blockIdx.x % (NG / FG);
    int g0  = gt * FG;

    if (tid < NBAS * 3) {
        int k = tid / 3, p = tid % 3;
        float wmu  = expf(mu[p]);
        float wstd = 1.0f / (expf(sigma[p]) + EPSF);
        float e = eps1[(b * NBAS + k) * NP + p];
        float u = b_u [(b * NBAS + k) * NP + p];
        ssw[tid] = __fadd_rn(wmu, __fmul_rn(wstd, e));
        ssb[tid] = __fmul_rn(PI2F, u);
    }
    if (tid < NBAS) srw[tid] = rw[tid];
    __syncthreads();

    // Phase 1: pos = n_h1 + fourier for tile + halo
    for (int e = tid; e < FGH * 9; e += FTHREADS) {
        int jj = e / 9;
        int cp = e % 9;
        int c = cp / 3, p = cp % 3;
        int g = g0 - HALO + jj;
        float pos = 0.f;
        if (g >= 0 && g < NG) {
            int idx = ((b * NG + g) * CH + c) * NP + p;
            float h0 = 0.f, h1 = 0.f;
#pragma unroll
            for (int s = 0; s < SPLIT; s++) {
                h0 += g_ph0[s * ELEMS + idx];
                h1 += g_ph1[s * ELEMS + idx];
            }
            float nh1 = h1 / (h0 + EPSF);

            float xg = x_g[(b * NG + g) * CH + c];
            float acc = 0.f;
#pragma unroll
            for (int k = 0; k < NBAS; k++) {
                float arg = __fadd_rn(__fmul_rn(ssw[k * 3 + p], xg), ssb[k * 3 + p]);
                acc = __fadd_rn(acc, __fmul_rn(srw[k], cos_red(arg)));
            }
            float fp = SQRT_2_OVER_NBAS * acc;
            pos = nh1 + fp;

            if (jj >= HALO && jj < HALO + FG) {
                out[OFF_NH1 + idx] = nh1;
                out[OFF_FP  + idx] = fp;
                out[OFF_H0  + idx] = h0;
            }
        }
        spos[e] = pos;
    }
    __syncthreads();

    // Phase 2: depthwise conv along g + per-cp partial stats
    {
        int cp = tid / FG;         // 0..8
        int j  = tid % FG;         // 0..63
        int c = cp / 3, p = cp % 3;
        int g = g0 + j;

        const float* w; const float* bias; int ksz, pad;
        if (p == 0)      { w = w1; bias = b1; ksz = 3; pad = 1; }
        else if (p == 1) { w = w2; bias = b2; ksz = 5; pad = 2; }
        else             { w = w3; bias = b3; ksz = 9; pad = 4; }

        float acc = bias[c];
        int jj0 = j - pad + HALO;
        for (int t = 0; t < ksz; t++)
            acc = fmaf(w[c * ksz + t], spos[(jj0 + t) * 9 + cp], acc);

        g_conv[((b * NG + g) * CH + c) * NP + p] = acc;
        ssum[cp * FG + j] = acc;
        ssq [cp * FG + j] = acc * acc;
    }
    __syncthreads();

    {
        int cp = tid / FG;
        int j  = tid % FG;
        int base = cp * FG;
        for (int st = FG / 2; st > 0; st >>= 1) {
            if (j < st) {
                ssum[base + j] += ssum[base + j + st];
                ssq [base + j] += ssq [base + j + st];
            }
            __syncthreads();
        }
        if (j == 0) {
            g_psum[cp * FBLOCKS + blockIdx.x] = ssum[base];
            g_psq [cp * FBLOCKS + blockIdx.x] = ssq [base];
        }
    }
}

// ---------------- kernel 5: BN finalize + apply + n_f + final linear (18 -> 64) ----------------
#define GW_STRIDE 19
__global__ __launch_bounds__(256) void k5_final(
    const float* __restrict__ gamma, const float* __restrict__ beta,
    const float* __restrict__ gw,    const float* __restrict__ gb,
    float* __restrict__ out)
{
    __shared__ float sgw[OC * GW_STRIDE];
    __shared__ float sgb[OC];
    __shared__ float sA[9], sB[9];
    __shared__ float feat[K5_POS * 18];

    int tid = threadIdx.x;
    int pos0 = blockIdx.x * K5_POS;

    for (int t = tid; t < OC * 18; t += 256)
        sgw[(t / 18) * GW_STRIDE + (t % 18)] = gw[t];
    if (tid < OC) sgb[tid] = gb[tid];

    if (tid < 9) {
        float s = 0.f, q = 0.f;
#pragma unroll 8
        for (int i = 0; i < FBLOCKS; i++) {
            s += g_psum[tid * FBLOCKS + i];
            q += g_psq [tid * FBLOCKS + i];
        }
        const float invn = 1.0f / (float)(NB * NG);
        float m   = s * invn;
        float var = q * invn - m * m;
        float rs  = rsqrtf(var + BNEPS);
        int c = tid / 3, p = tid % 3;
        float ga = gamma[p * CH + c];
        float be = beta [p * CH + c];
        sA[tid] = rs * ga;
        sB[tid] = be - m * rs * ga;
    }
    __syncthreads();

    for (int t = tid; t < K5_POS * 18; t += 256) {
        int pl = t / 18, k = t % 18;
        int pos = pos0 + pl;
        float v;
        if (k < 9) {
            v = out[OFF_H0 + pos * 9 + k];
        } else {
            int cp = k - 9;
            v = fmaf(g_conv[pos * 9 + cp], sA[cp], sB[cp]);
            out[OFF_NF + pos * 9 + cp] = v;
        }
        feat[pl * 18 + k] = v;
    }
    __syncthreads();

    int oc = tid % OC;
    int pp = tid / OC;
#pragma unroll
    for (int i = 0; i < K5_POS / 4; i++) {
        int pl = pp * (K5_POS / 4) + i;
        float acc = sgb[oc];
#pragma unroll
        for (int f = 0; f < 18; f++)
            acc = fmaf(feat[pl * 18 + f], sgw[oc * GW_STRIDE + f], acc);
        out[(pos0 + pl) * OC + oc] = acc;
    }
}

// ---------------- launch ----------------
extern "C" void kernel_launch(void* const* d_in, const int* in_sizes, int n_in,
                              void* d_out, int out_size)
{
    const float* x_c   = (const float*)d_in[0];
    const float* y_c   = (const float*)d_in[1];
    const float* x_g   = (const float*)d_in[2];
    const float* sigma = (const float*)d_in[3];
    const float* mu    = (const float*)d_in[4];
    const float* eps1  = (const float*)d_in[5];
    const float* b_u   = (const float*)d_in[6];
    const float* rw    = (const float*)d_in[7];
    const float* w1    = (const float*)d_in[8];
    const float* b1    = (const float*)d_in[9];
    const float* w2    = (const float*)d_in[10];
    const float* b2    = (const float*)d_in[11];
    const float* w3    = (const float*)d_in[12];
    const float* b3    = (const float*)d_in[13];
    const float* gam   = (const float*)d_in[14];
    const float* bet   = (const float*)d_in[15];
    const float* gw    = (const float*)d_in[16];
    const float* gb    = (const float*)d_in[17];
    float* out = (float*)d_out;

    k1_rbf<<<NB * GTILES * SPLIT, CH * TILE_G>>>(x_c, y_c, x_g, sigma);
    kF_fused<<<FBLOCKS, FTHREADS>>>(x_g, sigma, mu, eps1, b_u, rw,
                                    w1, b1, w2, b2, w3, b3, out);
    k5_final<<<K5_BLOCKS, 256>>>(gam, bet, gw, gb, out);
}

// round 4
// speedup vs baseline: 1.1332x; 1.0687x over previous
#include <cuda_runtime.h>

// ---------------- problem constants ----------------
#define NB 4
#define NC 512
#define NG 2048
#define CH 3
#define NP 3
#define NBAS 10
#define OC 64
#define EPSF 1e-6f
#define BNEPS 1e-5f
#define LOG2E_F 1.4426950408889634f
#define PI2F 6.283185307179586f
#define INV2PI_F 0.15915494309189535f
#define PI2_D 6.283185307179586
#define SQRT_2_OVER_NBAS 0.4472135954999579f
#define MAGICF 12582912.0f   // 1.5 * 2^23

#define SPLIT 8
#define NCHUNK (NC / SPLIT)   // 64
#define TILE_G 64
#define GTILES (NG / TILE_G)  // 32

#define ELEMS (NB * NG * CH * NP)  // 73728

// fused combine/conv kernel tiling
#define FG 16                       // g-tile per block
#define FBLOCKS (NB * (NG / FG))    // 512
#define FTHREADS 224                // 7 warps
#define HALO 4
#define FGH (FG + 2 * HALO)         // 24
#define FCONV (9 * FG)              // 144 conv threads

// final kernel tiling
#define K5_POS 32
#define K5_BLOCKS ((NB * NG) / K5_POS)  // 256

// output offsets (flattened tuple concat: y_out, n_f, fourier, n_h1, h0_f)
#define OFF_NF  (NB * NG * OC)        // 524288
#define OFF_FP  (OFF_NF + ELEMS)      // 598016
#define OFF_NH1 (OFF_FP + ELEMS)      // 671744
#define OFF_H0  (OFF_NH1 + ELEMS)     // 745472

// ---------------- scratch (no allocs allowed) ----------------
__device__ float g_ph0[SPLIT * ELEMS];
__device__ float g_ph1[SPLIT * ELEMS];
__device__ float g_conv[ELEMS];             // conv output (pre-BN)
__device__ float g_psum[9 * FBLOCKS];       // per-cp per-block partial sums
__device__ float g_psq [9 * FBLOCKS];       // per-cp per-block partial sum-squares

// ---------------- f32x2 packed helpers ----------------
typedef unsigned long long u64t;

__device__ __forceinline__ float ex2f(float x) {
    float y;
    asm("ex2.approx.ftz.f32 %0, %1;" : "=f"(y) : "f"(x));
    return y;
}
__device__ __forceinline__ u64t f2_add(u64t a, u64t b) {
    u64t r; asm("add.rn.f32x2 %0, %1, %2;" : "=l"(r) : "l"(a), "l"(b)); return r;
}
__device__ __forceinline__ u64t f2_mul(u64t a, u64t b) {
    u64t r; asm("mul.rn.f32x2 %0, %1, %2;" : "=l"(r) : "l"(a), "l"(b)); return r;
}
__device__ __forceinline__ u64t f2_fma(u64t a, u64t b, u64t c) {
    u64t r; asm("fma.rn.f32x2 %0, %1, %2, %3;" : "=l"(r) : "l"(a), "l"(b), "l"(c)); return r;
}
__device__ __forceinline__ u64t f2_pack(float lo, float hi) {
    u64t r; asm("mov.b64 %0, {%1, %2};" : "=l"(r) : "f"(lo), "f"(hi)); return r;
}
__device__ __forceinline__ void f2_unpack(u64t v, float& lo, float& hi) {
    asm("mov.b64 {%0, %1}, %2;" : "=f"(lo), "=f"(hi) : "l"(v));
}

// ---------------- kernel 1: RBF pairwise partial sums ----------------
// grid: NB * GTILES * SPLIT = 1024 blocks, block: 192 threads (6 warps).
// warp w: c = w % 3 (uniform), g = gt*64 + (w/3)*32 + lane.
// p0/p1 exps on the MUFU pipe; p2's exp on the FMA/ALU pipes (exp2 poly)
// so the MUFU bottleneck drops from 6 to 4 ex2 per packed iteration.
__global__ __launch_bounds__(CH * TILE_G) void k1_rbf(
    const float* __restrict__ x_c, const float* __restrict__ y_c,
    const float* __restrict__ x_g, const float* __restrict__ sigma)
{
    __shared__ __align__(8) float sxn[NCHUNK * CH];  // negated x, pair-interleaved
    __shared__ __align__(8) float syp[NCHUNK * CH];

    int unit = blockIdx.x;
    int s  = unit % SPLIT;
    int gt = (unit / SPLIT) % GTILES;
    int b  = unit / (SPLIT * GTILES);

    int lane = threadIdx.x & 31;
    int w    = threadIdx.x >> 5;       // 0..5
    int c    = w % 3;                  // uniform per warp
    int g    = gt * TILE_G + (w / 3) * 32 + lane;
    int n0   = s * NCHUNK;

    const float* xb = x_c + (b * NC + n0) * CH;
    const float* yb = y_c + (b * NC + n0) * CH;
    for (int i = threadIdx.x; i < NCHUNK * CH; i += blockDim.x) {
        int n = i / CH, cc = i % CH;
        int slot = ((n >> 1) * CH + cc) * 2 + (n & 1);
        sxn[slot] = -xb[i];
        syp[slot] =  yb[i];
    }
    __syncthreads();

    float xg = x_g[(b * NG + g) * CH + c];
    u64t xg2 = f2_pack(xg, xg);

    float s0 = expf(sigma[0]) + EPSF;
    float s1 = expf(sigma[1]) + EPSF;
    float s2 = expf(sigma[2]) + EPSF;
    float k0 = -0.5f * LOG2E_F / (s0 * s0);
    float k1 = -0.5f * LOG2E_F / (s1 * s1);
    float k2 = -0.5f * LOG2E_F / (s2 * s2);
    u64t k02 = f2_pack(k0, k0);
    u64t k12 = f2_pack(k1, k1);
    u64t k22 = f2_pack(k2, k2);

    // packed exp2-poly constants (2^f = 1 + f*P4(f), |f|<=0.5, rel err ~3e-6)
    const u64t c1x2 = f2_pack(0.693147182f, 0.693147182f);
    const u64t c2x2 = f2_pack(0.240226479f, 0.240226479f);
    const u64t c3x2 = f2_pack(0.0555041087f, 0.0555041087f);
    const u64t c4x2 = f2_pack(0.00961843737f, 0.00961843737f);
    const u64t c5x2 = f2_pack(0.00133335581f, 0.00133335581f);
    const u64t onex2 = f2_pack(1.0f, 1.0f);

    u64t h0a = 0, h0b = 0, h0c = 0;
    u64t h1a = 0, h1b = 0, h1c = 0;

    const u64t* sx2 = (const u64t*)sxn;
    const u64t* sy2 = (const u64t*)syp;

#pragma unroll 8
    for (int n2 = 0; n2 < NCHUNK / 2; n2++) {
        u64t xv = sx2[n2 * CH + c];   // broadcast LDS.64 (warp-uniform addr)
        u64t yv = sy2[n2 * CH + c];
        u64t d2 = f2_add(xg2, xv);    // xg - x  (x pre-negated)
        u64t t2 = f2_mul(d2, d2);

        float alo, ahi;
        // p0, p1 -> MUFU
        u64t a0 = f2_mul(t2, k02);
        f2_unpack(a0, alo, ahi);
        u64t w0 = f2_pack(ex2f(alo), ex2f(ahi));
        h0a = f2_add(h0a, w0);
        h1a = f2_fma(w0, yv, h1a);

        u64t a1 = f2_mul(t2, k12);
        f2_unpack(a1, alo, ahi);
        u64t w1 = f2_pack(ex2f(alo), ex2f(ahi));
        h0b = f2_add(h0b, w1);
        h1b = f2_fma(w1, yv, h1b);

        // p2 -> FMA/ALU-pipe exp2
        {
            float a2lo, a2hi;
            f2_unpack(f2_mul(t2, k22), a2lo, a2hi);
            a2lo = fmaxf(a2lo, -120.f);
            a2hi = fmaxf(a2hi, -120.f);
            float zlo = a2lo + MAGICF;
            float zhi = a2hi + MAGICF;
            int ilo = __float_as_int(zlo) << 23;
            int ihi = __float_as_int(zhi) << 23;
            float flo = a2lo - (zlo - MAGICF);
            float fhi = a2hi - (zhi - MAGICF);
            u64t fv = f2_pack(flo, fhi);
            u64t pp = f2_fma(fv, c5x2, c4x2);
            pp = f2_fma(fv, pp, c3x2);
            pp = f2_fma(fv, pp, c2x2);
            pp = f2_fma(fv, pp, c1x2);
            pp = f2_fma(fv, pp, onex2);
            float plo, phi;
            f2_unpack(pp, plo, phi);
            float wlo = __int_as_float(__float_as_int(plo) + ilo);
            float whi = __int_as_float(__float_as_int(phi) + ihi);
            u64t w2 = f2_pack(wlo, whi);
            h0c = f2_add(h0c, w2);
            h1c = f2_fma(w2, yv, h1c);
        }
    }

    float lo, hi;
    int base = ((b * NG + g) * CH + c) * NP;
    int off  = s * ELEMS + base;
    f2_unpack(h0a, lo, hi); g_ph0[off + 0] = lo + hi;
    f2_unpack(h0b, lo, hi); g_ph0[off + 1] = lo + hi;
    f2_unpack(h0c, lo, hi); g_ph0[off + 2] = lo + hi;
    f2_unpack(h1a, lo, hi); g_ph1[off + 0] = lo + hi;
    f2_unpack(h1b, lo, hi); g_ph1[off + 1] = lo + hi;
    f2_unpack(h1c, lo, hi); g_ph1[off + 2] = lo + hi;
}

// accurate-enough cos for args up to ~1e5: exact-multiple reduction via one DFMA,
// then hardware cos on |r| <= pi (abs err ~2e-7).
__device__ __forceinline__ float cos_red(float arg) {
    float n = rintf(arg * INV2PI_F);
    float r = (float)__fma_rn((double)(-n), PI2_D, (double)arg);
    return __cosf(r);
}

// ---------------- kernel F: combine + Fourier prior + depthwise conv + BN partials ----------------
// grid: 512 blocks (b x g-tile of 16), 224 threads.
// Phase 1: 1 elem/thread (216 active) -> high-MLP split-combine + Fourier.
// Phase 2: 144 threads conv from smem; width-16 shuffle reduce for BN partials.
__global__ __launch_bounds__(FTHREADS) void kF_fused(
    const float* __restrict__ x_g, const float* __restrict__ sigma,
    const float* __restrict__ mu,  const float* __restrict__ eps1,
    const float* __restrict__ b_u, const float* __restrict__ rw,
    const float* __restrict__ w1, const float* __restrict__ b1,
    const float* __restrict__ w2, const float* __restrict__ b2,
    const float* __restrict__ w3, const float* __restrict__ b3,
    float* __restrict__ out)
{
    __shared__ float spos[FGH * 9];       // 216
    __shared__ float ssw[NBAS * 3];
    __shared__ float ssb[NBAS * 3];
    __shared__ float srw[NBAS];

    int tid = threadIdx.x;
    int b   = blockIdx.x / (NG / FG);
    int gt  = blockIdx.x % (NG / FG);
    int g0  = gt * FG;

    if (tid < NBAS * 3) {
        int k = tid / 3, p = tid % 3;
        float wmu  = expf(mu[p]);
        float wstd = 1.0f / (expf(sigma[p]) + EPSF);
        float e = eps1[(b * NBAS + k) * NP + p];
        float u = b_u [(b * NBAS + k) * NP + p];
        ssw[tid] = __fadd_rn(wmu, __fmul_rn(wstd, e));
        ssb[tid] = __fmul_rn(PI2F, u);
    }
    if (tid < NBAS) srw[tid] = rw[tid];
    __syncthreads();

    // Phase 1: pos = n_h1 + fourier, one element per thread
    if (tid < FGH * 9) {
        int jj = tid / 9;
        int cp = tid % 9;
        int c = cp / 3, p = cp % 3;
        int g = g0 - HALO + jj;
        float pos = 0.f;
        if (g >= 0 && g < NG) {
            int idx = ((b * NG + g) * CH + c) * NP + p;
            float h0 = 0.f, h1 = 0.f;
#pragma unroll
            for (int s = 0; s < SPLIT; s++) {
                h0 += g_ph0[s * ELEMS + idx];
                h1 += g_ph1[s * ELEMS + idx];
            }
            float nh1 = h1 / (h0 + EPSF);

            float xg = x_g[(b * NG + g) * CH + c];
            float acc = 0.f;
#pragma unroll
            for (int k = 0; k < NBAS; k++) {
                float arg = __fadd_rn(__fmul_rn(ssw[k * 3 + p], xg), ssb[k * 3 + p]);
                acc = __fadd_rn(acc, __fmul_rn(srw[k], cos_red(arg)));
            }
            float fp = SQRT_2_OVER_NBAS * acc;
            pos = nh1 + fp;

            if (jj >= HALO && jj < HALO + FG) {
                out[OFF_NH1 + idx] = nh1;
                out[OFF_FP  + idx] = fp;
                out[OFF_H0  + idx] = h0;
            }
        }
        spos[tid] = pos;
    }
    __syncthreads();

    // Phase 2: depthwise conv along g + per-cp partial stats
    float acc = 0.f, sq = 0.f;
    if (tid < FCONV) {
        int cp = tid >> 4;        // tid / 16: 0..8
        int j  = tid & 15;        // 0..15
        int c = cp / 3, p = cp % 3;
        int g = g0 + j;

        const float* w; const float* bias; int ksz, pad;
        if (p == 0)      { w = w1; bias = b1; ksz = 3; pad = 1; }
        else if (p == 1) { w = w2; bias = b2; ksz = 5; pad = 2; }
        else             { w = w3; bias = b3; ksz = 9; pad = 4; }

        acc = bias[c];
        int jj0 = j - pad + HALO;
        for (int t = 0; t < ksz; t++)
            acc = fmaf(w[c * ksz + t], spos[(jj0 + t) * 9 + cp], acc);

        g_conv[((b * NG + g) * CH + c) * NP + p] = acc;
        sq = acc * acc;
    }
    // width-16 segmented shuffle reduce (all 7 full warps participate)
#pragma unroll
    for (int st = 8; st > 0; st >>= 1) {
        acc += __shfl_down_sync(0xffffffffu, acc, st, 16);
        sq  += __shfl_down_sync(0xffffffffu, sq,  st, 16);
    }
    if (tid < FCONV && (tid & 15) == 0) {
        int cp = tid >> 4;
        g_psum[cp * FBLOCKS + blockIdx.x] = acc;
        g_psq [cp * FBLOCKS + blockIdx.x] = sq;
    }
}

// ---------------- kernel 5: BN finalize + apply + n_f + final linear (18 -> 64) ----------------
#define GW_STRIDE 19
__global__ __launch_bounds__(256) void k5_final(
    const float* __restrict__ gamma, const float* __restrict__ beta,
    const float* __restrict__ gw,    const float* __restrict__ gb,
    float* __restrict__ out)
{
    __shared__ float sgw[OC * GW_STRIDE];
    __shared__ float sgb[OC];
    __shared__ float sA[9], sB[9];
    __shared__ float feat[K5_POS * 18];

    int tid = threadIdx.x;
    int pos0 = blockIdx.x * K5_POS;

    for (int t = tid; t < OC * 18; t += 256)
        sgw[(t / 18) * GW_STRIDE + (t % 18)] = gw[t];
    if (tid < OC) sgb[tid] = gb[tid];

    // BN finalize: 16 lanes per cp, coalesced strided loads + width-16 shuffle
    {
        float s = 0.f, q = 0.f;
        int cp = tid >> 4, l = tid & 15;
        if (tid < 144) {
            for (int k = l; k < FBLOCKS; k += 16) {
                s += g_psum[cp * FBLOCKS + k];
                q += g_psq [cp * FBLOCKS + k];
            }
        }
#pragma unroll
        for (int st = 8; st > 0; st >>= 1) {
            s += __shfl_down_sync(0xffffffffu, s, st, 16);
            q += __shfl_down_sync(0xffffffffu, q, st, 16);
        }
        if (tid < 144 && l == 0) {
            const float invn = 1.0f / (float)(NB * NG);
            float m   = s * invn;
            float var = q * invn - m * m;
            float rs  = rsqrtf(var + BNEPS);
            int c = cp / 3, p = cp % 3;
            float ga = gamma[p * CH + c];
            float be = beta [p * CH + c];
            sA[cp] = rs * ga;
            sB[cp] = be - m * rs * ga;
        }
    }
    __syncthreads();

    for (int t = tid; t < K5_POS * 18; t += 256) {
        int pl = t / 18, k = t % 18;
        int pos = pos0 + pl;
        float v;
        if (k < 9) {
            v = out[OFF_H0 + pos * 9 + k];
        } else {
            int cp = k - 9;
            v = fmaf(g_conv[pos * 9 + cp], sA[cp], sB[cp]);
            out[OFF_NF + pos * 9 + cp] = v;
        }
        feat[pl * 18 + k] = v;
    }
    __syncthreads();

    int oc = tid % OC;
    int pp = tid / OC;
#pragma unroll
    for (int i = 0; i < K5_POS / 4; i++) {
        int pl = pp * (K5_POS / 4) + i;
        float acc = sgb[oc];
#pragma unroll
        for (int f = 0; f < 18; f++)
            acc = fmaf(feat[pl * 18 + f], sgw[oc * GW_STRIDE + f], acc);
        out[(pos0 + pl) * OC + oc] = acc;
    }
}

// ---------------- launch ----------------
extern "C" void kernel_launch(void* const* d_in, const int* in_sizes, int n_in,
                              void* d_out, int out_size)
{
    const float* x_c   = (const float*)d_in[0];
    const float* y_c   = (const float*)d_in[1];
    const float* x_g   = (const float*)d_in[2];
    const float* sigma = (const float*)d_in[3];
    const float* mu    = (const float*)d_in[4];
    const float* eps1  = (const float*)d_in[5];
    const float* b_u   = (const float*)d_in[6];
    const float* rw    = (const float*)d_in[7];
    const float* w1    = (const float*)d_in[8];
    const float* b1    = (const float*)d_in[9];
    const float* w2    = (const float*)d_in[10];
    const float* b2    = (const float*)d_in[11];
    const float* w3    = (const float*)d_in[12];
    const float* b3    = (const float*)d_in[13];
    const float* gam   = (const float*)d_in[14];
    const float* bet   = (const float*)d_in[15];
    const float* gw    = (const float*)d_in[16];
    const float* gb    = (const float*)d_in[17];
    float* out = (float*)d_out;

    k1_rbf<<<NB * GTILES * SPLIT, CH * TILE_G>>>(x_c, y_c, x_g, sigma);
    kF_fused<<<FBLOCKS, FTHREADS>>>(x_g, sigma, mu, eps1, b_u, rw,
                                    w1, b1, w2, b2, w3, b3, out);
    k5_final<<<K5_BLOCKS, 256>>>(gam, bet, gw, gb, out);
}

// round 5
// speedup vs baseline: 1.2140x; 1.0713x over previous
#include <cuda_runtime.h>

// ---------------- problem constants ----------------
#define NB 4
#define NC 512
#define NG 2048
#define CH 3
#define NP 3
#define NBAS 10
#define OC 64
#define EPSF 1e-6f
#define BNEPS 1e-5f
#define LOG2E_F 1.4426950408889634f
#define PI2F 6.283185307179586f
#define INV2PI_F 0.15915494309189535f
#define PI2_D 6.2831853071795864769
#define SQRT_2_OVER_NBAS 0.4472135954999579f

#define SPLIT 8
#define NCHUNK (NC / SPLIT)   // 64
#define TILE_G 64
#define GTILES (NG / TILE_G)  // 32

#define ELEMS (NB * NG * CH * NP)  // 73728

// fused combine/conv kernel tiling
#define FG 16                       // g-tile per block
#define FBLOCKS (NB * (NG / FG))    // 512
#define FTHREADS 224                // 7 warps
#define HALO 4
#define FGH (FG + 2 * HALO)         // 24
#define FCONV (9 * FG)              // 144 conv threads

// final kernel tiling
#define K5_POS 32
#define K5_BLOCKS ((NB * NG) / K5_POS)  // 256

// output offsets (flattened tuple concat: y_out, n_f, fourier, n_h1, h0_f)
#define OFF_NF  (NB * NG * OC)        // 524288
#define OFF_FP  (OFF_NF + ELEMS)      // 598016
#define OFF_NH1 (OFF_FP + ELEMS)      // 671744
#define OFF_H0  (OFF_NH1 + ELEMS)     // 745472

// ---------------- scratch (no allocs allowed) ----------------
__device__ float g_ph0[SPLIT * ELEMS];
__device__ float g_ph1[SPLIT * ELEMS];
__device__ float g_conv[ELEMS];             // conv output (pre-BN)
__device__ float g_psum[9 * FBLOCKS];       // per-cp per-block partial sums
__device__ float g_psq [9 * FBLOCKS];       // per-cp per-block partial sum-squares

__device__ __forceinline__ float ex2f(float x) {
    float y;
    asm("ex2.approx.ftz.f32 %0, %1;" : "=f"(y) : "f"(x));
    return y;
}

// ---------------- kernel 1: RBF pairwise partial sums (lean scalar) ----------------
// grid: NB * GTILES * SPLIT = 1024 blocks (all co-resident), block: 192 threads.
// warp w: c = w % 3 (uniform), g = gt*64 + (w/3)*32 + lane.
// Scalar math, float2 shared loads, 12 even/odd accumulators for ILP.
// ~30 issued instrs + 6 MUFU per 2 context points -> MUFU-pipe-bound.
__global__ __launch_bounds__(CH * TILE_G) void k1_rbf(
    const float* __restrict__ x_c, const float* __restrict__ y_c,
    const float* __restrict__ x_g, const float* __restrict__ sigma)
{
    __shared__ __align__(8) float sxp[NCHUNK * CH];  // pair-interleaved x
    __shared__ __align__(8) float syp[NCHUNK * CH];

    int unit = blockIdx.x;
    int s  = unit % SPLIT;
    int gt = (unit / SPLIT) % GTILES;
    int b  = unit / (SPLIT * GTILES);

    int lane = threadIdx.x & 31;
    int w    = threadIdx.x >> 5;       // 0..5
    int c    = w % 3;                  // uniform per warp
    int g    = gt * TILE_G + (w / 3) * 32 + lane;
    int n0   = s * NCHUNK;

    const float* xb = x_c + (b * NC + n0) * CH;
    const float* yb = y_c + (b * NC + n0) * CH;
    // stage: element (n, cc) -> slot ((n/2)*CH + cc)*2 + (n&1)
    for (int i = threadIdx.x; i < NCHUNK * CH; i += blockDim.x) {
        int n = i / CH, cc = i % CH;
        int slot = ((n >> 1) * CH + cc) * 2 + (n & 1);
        sxp[slot] = xb[i];
        syp[slot] = yb[i];
    }
    __syncthreads();

    float xg = x_g[(b * NG + g) * CH + c];

    // fold -0.5 * log2(e) / (scale+eps)^2 into one multiply per p
    float s0 = expf(sigma[0]) + EPSF;
    float s1 = expf(sigma[1]) + EPSF;
    float s2 = expf(sigma[2]) + EPSF;
    float k0 = -0.5f * LOG2E_F / (s0 * s0);
    float k1 = -0.5f * LOG2E_F / (s1 * s1);
    float k2 = -0.5f * LOG2E_F / (s2 * s2);

    float h00e = 0.f, h01e = 0.f, h02e = 0.f;
    float h00o = 0.f, h01o = 0.f, h02o = 0.f;
    float h10e = 0.f, h11e = 0.f, h12e = 0.f;
    float h10o = 0.f, h11o = 0.f, h12o = 0.f;

    const float2* sx2 = (const float2*)sxp;
    const float2* sy2 = (const float2*)syp;

#pragma unroll 8
    for (int n2 = 0; n2 < NCHUNK / 2; n2++) {
        float2 xv = sx2[n2 * CH + c];   // broadcast LDS.64 (warp-uniform addr)
        float2 yv = sy2[n2 * CH + c];
        float d0 = xg - xv.x;
        float d1 = xg - xv.y;
        float t0 = d0 * d0;
        float t1 = d1 * d1;
        float wv;
        wv = ex2f(t0 * k0); h00e += wv; h10e = fmaf(wv, yv.x, h10e);
        wv = ex2f(t1 * k0); h00o += wv; h10o = fmaf(wv, yv.y, h10o);
        wv = ex2f(t0 * k1); h01e += wv; h11e = fmaf(wv, yv.x, h11e);
        wv = ex2f(t1 * k1); h01o += wv; h11o = fmaf(wv, yv.y, h11o);
        wv = ex2f(t0 * k2); h02e += wv; h12e = fmaf(wv, yv.x, h12e);
        wv = ex2f(t1 * k2); h02o += wv; h12o = fmaf(wv, yv.y, h12o);
    }

    int base = ((b * NG + g) * CH + c) * NP;
    int off  = s * ELEMS + base;
    g_ph0[off + 0] = h00e + h00o;
    g_ph0[off + 1] = h01e + h01o;
    g_ph0[off + 2] = h02e + h02o;
    g_ph1[off + 0] = h10e + h10o;
    g_ph1[off + 1] = h11e + h11o;
    g_ph1[off + 2] = h12e + h12o;
}

// fp32 Cody-Waite cos for args up to ~2e5: two single-rounding FMAs remove
// n*2pi (product exact inside FMA), then hardware cos on |r| <= pi+eps.
// abs err ~7e-7, zero FP64-pipe traffic.
__device__ __forceinline__ float cos_red(float arg) {
    const float F2PI     = (float)PI2_D;                      // fl(2pi)
    const float F2PI_RES = (float)(PI2_D - (double)((float)PI2_D));
    float n = rintf(arg * INV2PI_F);
    float r = fmaf(-n, F2PI, arg);
    r = fmaf(-n, F2PI_RES, r);
    return __cosf(r);
}

// ---------------- kernel F: combine + Fourier prior + depthwise conv + BN partials ----------------
// grid: 512 blocks (b x g-tile of 16), 224 threads.
__global__ __launch_bounds__(FTHREADS) void kF_fused(
    const float* __restrict__ x_g, const float* __restrict__ sigma,
    const float* __restrict__ mu,  const float* __restrict__ eps1,
    const float* __restrict__ b_u, const float* __restrict__ rw,
    const float* __restrict__ w1, const float* __restrict__ b1,
    const float* __restrict__ w2, const float* __restrict__ b2,
    const float* __restrict__ w3, const float* __restrict__ b3,
    float* __restrict__ out)
{
    __shared__ float spos[FGH * 9];       // 216
    __shared__ float ssw[NBAS * 3];
    __shared__ float ssb[NBAS * 3];
    __shared__ float srw[NBAS];

    int tid = threadIdx.x;
    int b   = blockIdx.x / (NG / FG);
    int gt  = blockIdx.x % (NG / FG);
    int g0  = gt * FG;

    if (tid < NBAS * 3) {
        int k = tid / 3, p = tid % 3;
        float wmu  = expf(mu[p]);
        float wstd = 1.0f / (expf(sigma[p]) + EPSF);
        float e = eps1[(b * NBAS + k) * NP + p];
        float u = b_u [(b * NBAS + k) * NP + p];
        ssw[tid] = __fadd_rn(wmu, __fmul_rn(wstd, e));
        ssb[tid] = __fmul_rn(PI2F, u);
    }
    if (tid < NBAS) srw[tid] = rw[tid];
    __syncthreads();

    // Phase 1: pos = n_h1 + fourier, one element per thread
    if (tid < FGH * 9) {
        int jj = tid / 9;
        int cp = tid % 9;
        int c = cp / 3, p = cp % 3;
        int g = g0 - HALO + jj;
        float pos = 0.f;
        if (g >= 0 && g < NG) {
            int idx = ((b * NG + g) * CH + c) * NP + p;
            float h0 = 0.f, h1 = 0.f;
#pragma unroll
            for (int s = 0; s < SPLIT; s++) {
                h0 += g_ph0[s * ELEMS + idx];
                h1 += g_ph1[s * ELEMS + idx];
            }
            float nh1 = h1 / (h0 + EPSF);

            float xg = x_g[(b * NG + g) * CH + c];
            float acc = 0.f;
#pragma unroll
            for (int k = 0; k < NBAS; k++) {
                float arg = __fadd_rn(__fmul_rn(ssw[k * 3 + p], xg), ssb[k * 3 + p]);
                acc = __fadd_rn(acc, __fmul_rn(srw[k], cos_red(arg)));
            }
            float fp = SQRT_2_OVER_NBAS * acc;
            pos = nh1 + fp;

            if (jj >= HALO && jj < HALO + FG) {
                out[OFF_NH1 + idx] = nh1;
                out[OFF_FP  + idx] = fp;
                out[OFF_H0  + idx] = h0;
            }
        }
        spos[tid] = pos;
    }
    __syncthreads();

    // Phase 2: depthwise conv along g + per-cp partial stats
    float acc = 0.f, sq = 0.f;
    if (tid < FCONV) {
        int cp = tid >> 4;        // 0..8
        int j  = tid & 15;        // 0..15
        int c = cp / 3, p = cp % 3;
        int g = g0 + j;

        const float* w; const float* bias; int ksz, pad;
        if (p == 0)      { w = w1; bias = b1; ksz = 3; pad = 1; }
        else if (p == 1) { w = w2; bias = b2; ksz = 5; pad = 2; }
        else             { w = w3; bias = b3; ksz = 9; pad = 4; }

        acc = bias[c];
        int jj0 = j - pad + HALO;
        for (int t = 0; t < ksz; t++)
            acc = fmaf(w[c * ksz + t], spos[(jj0 + t) * 9 + cp], acc);

        g_conv[((b * NG + g) * CH + c) * NP + p] = acc;
        sq = acc * acc;
    }
    // width-16 segmented shuffle reduce
#pragma unroll
    for (int st = 8; st > 0; st >>= 1) {
        acc += __shfl_down_sync(0xffffffffu, acc, st, 16);
        sq  += __shfl_down_sync(0xffffffffu, sq,  st, 16);
    }
    if (tid < FCONV && (tid & 15) == 0) {
        int cp = tid >> 4;
        g_psum[cp * FBLOCKS + blockIdx.x] = acc;
        g_psq [cp * FBLOCKS + blockIdx.x] = sq;
    }
}

// ---------------- kernel 5: BN finalize + apply + n_f + final linear (18 -> 64) ----------------
#define GW_STRIDE 19
__global__ __launch_bounds__(256) void k5_final(
    const float* __restrict__ gamma, const float* __restrict__ beta,
    const float* __restrict__ gw,    const float* __restrict__ gb,
    float* __restrict__ out)
{
    __shared__ float sgw[OC * GW_STRIDE];
    __shared__ float sgb[OC];
    __shared__ float sA[9], sB[9];
    __shared__ float feat[K5_POS * 18];

    int tid = threadIdx.x;
    int pos0 = blockIdx.x * K5_POS;

    for (int t = tid; t < OC * 18; t += 256)
        sgw[(t / 18) * GW_STRIDE + (t % 18)] = gw[t];
    if (tid < OC) sgb[tid] = gb[tid];

    // BN finalize: 16 lanes per cp, coalesced strided loads + width-16 shuffle
    {
        float s = 0.f, q = 0.f;
        int cp = tid >> 4, l = tid & 15;
        if (tid < 144) {
            for (int k = l; k < FBLOCKS; k += 16) {
                s += g_psum[cp * FBLOCKS + k];
                q += g_psq [cp * FBLOCKS + k];
            }
        }
#pragma unroll
        for (int st = 8; st > 0; st >>= 1) {
            s += __shfl_down_sync(0xffffffffu, s, st, 16);
            q += __shfl_down_sync(0xffffffffu, q, st, 16);
        }
        if (tid < 144 && l == 0) {
            const float invn = 1.0f / (float)(NB * NG);
            float m   = s * invn;
            float var = q * invn - m * m;
            float rs  = rsqrtf(var + BNEPS);
            int c = cp / 3, p = cp % 3;
            float ga = gamma[p * CH + c];
            float be = beta [p * CH + c];
            sA[cp] = rs * ga;
            sB[cp] = be - m * rs * ga;
        }
    }
    __syncthreads();

    for (int t = tid; t < K5_POS * 18; t += 256) {
        int pl = t / 18, k = t % 18;
        int pos = pos0 + pl;
        float v;
        if (k < 9) {
            v = out[OFF_H0 + pos * 9 + k];
        } else {
            int cp = k - 9;
            v = fmaf(g_conv[pos * 9 + cp], sA[cp], sB[cp]);
            out[OFF_NF + pos * 9 + cp] = v;
        }
        feat[pl * 18 + k] = v;
    }
    __syncthreads();

    int oc = tid % OC;
    int pp = tid / OC;
#pragma unroll
    for (int i = 0; i < K5_POS / 4; i++) {
        int pl = pp * (K5_POS / 4) + i;
        float acc = sgb[oc];
#pragma unroll
        for (int f = 0; f < 18; f++)
            acc = fmaf(feat[pl * 18 + f], sgw[oc * GW_STRIDE + f], acc);
        out[(pos0 + pl) * OC + oc] = acc;
    }
}

// ---------------- launch ----------------
extern "C" void kernel_launch(void* const* d_in, const int* in_sizes, int n_in,
                              void* d_out, int out_size)
{
    const float* x_c   = (const float*)d_in[0];
    const float* y_c   = (const float*)d_in[1];
    const float* x_g   = (const float*)d_in[2];
    const float* sigma = (const float*)d_in[3];
    const float* mu    = (const float*)d_in[4];
    const float* eps1  = (const float*)d_in[5];
    const float* b_u   = (const float*)d_in[6];
    const float* rw    = (const float*)d_in[7];
    const float* w1    = (const float*)d_in[8];
    const float* b1    = (const float*)d_in[9];
    const float* w2    = (const float*)d_in[10];
    const float* b2    = (const float*)d_in[11];
    const float* w3    = (const float*)d_in[12];
    const float* b3    = (const float*)d_in[13];
    const float* gam   = (const float*)d_in[14];
    const float* bet   = (const float*)d_in[15];
    const float* gw    = (const float*)d_in[16];
    const float* gb    = (const float*)d_in[17];
    float* out = (float*)d_out;

    k1_rbf<<<NB * GTILES * SPLIT, CH * TILE_G>>>(x_c, y_c, x_g, sigma);
    kF_fused<<<FBLOCKS, FTHREADS>>>(x_g, sigma, mu, eps1, b_u, rw,
                                    w1, b1, w2, b2, w3, b3, out);
    k5_final<<<K5_BLOCKS, 256>>>(gam, bet, gw, gb, out);
}